// round 7
// baseline (speedup 1.0000x reference)
#include <cuda_runtime.h>
#include <cuda_bf16.h>
#include <cstdint>
#include <cstddef>

#define HD    1024
#define OD    8192
#define BATCH 256
#define BK    16
#define BKP   24   // bf16 stride/row = 12 words; 12*g mod 32 hits distinct 4-bank groups -> conflict-free frags

typedef __nv_bfloat16 bf16;

// ---------------- persistent device scratch (no runtime allocation) ----------------
__device__ __align__(16) bf16 g_Wih_h[2 * HD * HD];
__device__ __align__(16) bf16 g_Wih_l[2 * HD * HD];
__device__ __align__(16) bf16 g_Whh_h[2 * HD * HD];
__device__ __align__(16) bf16 g_Whh_l[2 * HD * HD];
__device__ __align__(16) bf16 g_fcW_h[(size_t)OD * HD];
__device__ __align__(16) bf16 g_fcW_l[(size_t)OD * HD];
__device__ __align__(16) bf16 g_x_h [BATCH * HD];
__device__ __align__(16) bf16 g_x_l [BATCH * HD];
__device__ __align__(16) bf16 g_hid_h[2 * BATCH * HD];
__device__ __align__(16) bf16 g_hid_l[2 * BATCH * HD];
__device__ __align__(16) bf16 g_h0_h[2 * BATCH * HD];   // ping-pong layer-0 state
__device__ __align__(16) bf16 g_h0_l[2 * BATCH * HD];
__device__ __align__(16) bf16 g_out_h[2 * BATCH * HD];  // ping-pong top output (= layer-1 state)
__device__ __align__(16) bf16 g_out_l[2 * BATCH * HD];

// ---------------- small PTX helpers ----------------
__device__ __forceinline__ void cp_async16(void* sm, const void* gm) {
    unsigned s = (unsigned)__cvta_generic_to_shared(sm);
    asm volatile("cp.async.cg.shared.global [%0], [%1], 16;\n" :: "r"(s), "l"(gm));
}
__device__ __forceinline__ void cp_commit() { asm volatile("cp.async.commit_group;\n"); }
template<int N> __device__ __forceinline__ void cp_wait() {
    asm volatile("cp.async.wait_group %0;\n" :: "n"(N));
}
__device__ __forceinline__ void mma_bf16(float* c, const uint32_t* a, const uint32_t* b) {
    asm volatile(
        "mma.sync.aligned.m16n8k16.row.col.f32.bf16.bf16.f32 "
        "{%0,%1,%2,%3},{%4,%5,%6,%7},{%8,%9},{%0,%1,%2,%3};\n"
        : "+f"(c[0]), "+f"(c[1]), "+f"(c[2]), "+f"(c[3])
        : "r"(a[0]), "r"(a[1]), "r"(a[2]), "r"(a[3]), "r"(b[0]), "r"(b[1]));
}

// ---------------- fp32 -> (hi,lo) bf16 split ----------------
__global__ void split_kernel(const float* __restrict__ src,
                             bf16* __restrict__ h, bf16* __restrict__ l, int n) {
    for (int i = blockIdx.x * blockDim.x + threadIdx.x; i < n; i += gridDim.x * blockDim.x) {
        float v = src[i];
        bf16 hv = __float2bfloat16(v);
        h[i] = hv;
        l[i] = __float2bfloat16(v - __bfloat162float(hv));
    }
}

// ---------------- split-bf16 tiled GEMM ----------------
// C = A1@W1^T (+ A2@W2^T) + bias1 (+bias2), computed as Ah*Bh + Ah*Bl + Al*Bh.
// A row-major [M,K]; W row-major [N,K] (== "col" B operand for mma row.col).
// TANH: write tanh result as (hi,lo) bf16 pairs to Ch/Cl. Else: write fp32 to Cf.
template<int BM, int BN, int WM, int WN, int WARPS_M, int WARPS_N, bool DUAL, bool TANH>
__global__ void __launch_bounds__(WARPS_M * WARPS_N * 32)
gemm_bf16s(const bf16* __restrict__ A1h, const bf16* __restrict__ A1l,
           const bf16* __restrict__ W1h, const bf16* __restrict__ W1l,
           const bf16* __restrict__ A2h, const bf16* __restrict__ A2l,
           const bf16* __restrict__ W2h, const bf16* __restrict__ W2l,
           const float* __restrict__ bias1, const float* __restrict__ bias2,
           bf16* __restrict__ Ch, bf16* __restrict__ Cl, float* __restrict__ Cf,
           int K, int N)
{
    constexpr int THREADS = WARPS_M * WARPS_N * 32;
    constexpr int MT = WM / 16;
    constexpr int NT = WN / 8;

    __shared__ __align__(16) bf16 Ash[2][BM][BKP];
    __shared__ __align__(16) bf16 Asl[2][BM][BKP];
    __shared__ __align__(16) bf16 Bsh[2][BN][BKP];
    __shared__ __align__(16) bf16 Bsl[2][BN][BKP];

    const int tid  = threadIdx.x;
    const int lane = tid & 31;
    const int warp = tid >> 5;
    const int g    = lane >> 2;
    const int t4   = lane & 3;
    const int wmB  = (warp / WARPS_N) * WM;
    const int wnB  = (warp % WARPS_N) * WN;
    const int mBlock = blockIdx.y * BM;
    const int nBlock = blockIdx.x * BN;

    float acc[MT][NT][4];
#pragma unroll
    for (int i = 0; i < MT; i++)
#pragma unroll
        for (int j = 0; j < NT; j++)
#pragma unroll
            for (int q = 0; q < 4; q++) acc[i][j][q] = 0.f;

#pragma unroll
    for (int ph = 0; ph < (DUAL ? 2 : 1); ph++) {
        const bf16* Agh = (ph ? A2h : A1h) + (size_t)mBlock * K;
        const bf16* Agl = (ph ? A2l : A1l) + (size_t)mBlock * K;
        const bf16* Bgh = (ph ? W2h : W1h) + (size_t)nBlock * K;
        const bf16* Bgl = (ph ? W2l : W1l) + (size_t)nBlock * K;
        const int steps = K / BK;
        constexpr int TOT = (BM + BN) * 2;   // 16B chunks per (h or l) plane

        // prime buffer 0
        for (int i = tid; i < TOT; i += THREADS) {
            if (i < BM * 2) {
                int r = i >> 1, c = (i & 1) * 8;
                cp_async16(&Ash[0][r][c], Agh + (size_t)r * K + c);
                cp_async16(&Asl[0][r][c], Agl + (size_t)r * K + c);
            } else {
                int j = i - BM * 2, r = j >> 1, c = (j & 1) * 8;
                cp_async16(&Bsh[0][r][c], Bgh + (size_t)r * K + c);
                cp_async16(&Bsl[0][r][c], Bgl + (size_t)r * K + c);
            }
        }
        cp_commit();

        for (int kt = 0; kt < steps; kt++) {
            const int cur = kt & 1;
            if (kt + 1 < steps) {
                const int nxt = cur ^ 1;
                const int kb  = (kt + 1) * BK;
                for (int i = tid; i < TOT; i += THREADS) {
                    if (i < BM * 2) {
                        int r = i >> 1, c = (i & 1) * 8;
                        cp_async16(&Ash[nxt][r][c], Agh + (size_t)r * K + kb + c);
                        cp_async16(&Asl[nxt][r][c], Agl + (size_t)r * K + kb + c);
                    } else {
                        int j = i - BM * 2, r = j >> 1, c = (j & 1) * 8;
                        cp_async16(&Bsh[nxt][r][c], Bgh + (size_t)r * K + kb + c);
                        cp_async16(&Bsl[nxt][r][c], Bgl + (size_t)r * K + kb + c);
                    }
                }
                cp_commit();
                cp_wait<1>();
            } else {
                cp_wait<0>();
            }
            __syncthreads();

            uint32_t ah[MT][4], al[MT][4], bh[NT][2], bl[NT][2];
#pragma unroll
            for (int mt = 0; mt < MT; mt++) {
                int r = wmB + mt * 16 + g;
                ah[mt][0] = *(const uint32_t*)&Ash[cur][r    ][2 * t4];
                ah[mt][1] = *(const uint32_t*)&Ash[cur][r + 8][2 * t4];
                ah[mt][2] = *(const uint32_t*)&Ash[cur][r    ][2 * t4 + 8];
                ah[mt][3] = *(const uint32_t*)&Ash[cur][r + 8][2 * t4 + 8];
                al[mt][0] = *(const uint32_t*)&Asl[cur][r    ][2 * t4];
                al[mt][1] = *(const uint32_t*)&Asl[cur][r + 8][2 * t4];
                al[mt][2] = *(const uint32_t*)&Asl[cur][r    ][2 * t4 + 8];
                al[mt][3] = *(const uint32_t*)&Asl[cur][r + 8][2 * t4 + 8];
            }
#pragma unroll
            for (int nt = 0; nt < NT; nt++) {
                int cc = wnB + nt * 8 + g;
                bh[nt][0] = *(const uint32_t*)&Bsh[cur][cc][2 * t4];
                bh[nt][1] = *(const uint32_t*)&Bsh[cur][cc][2 * t4 + 8];
                bl[nt][0] = *(const uint32_t*)&Bsl[cur][cc][2 * t4];
                bl[nt][1] = *(const uint32_t*)&Bsl[cur][cc][2 * t4 + 8];
            }
#pragma unroll
            for (int mt = 0; mt < MT; mt++)
#pragma unroll
                for (int nt = 0; nt < NT; nt++) {
                    mma_bf16(acc[mt][nt], ah[mt], bh[nt]);   // hi*hi
                    mma_bf16(acc[mt][nt], ah[mt], bl[nt]);   // hi*lo
                    mma_bf16(acc[mt][nt], al[mt], bh[nt]);   // lo*hi
                }
            __syncthreads();
        }
    }

    // ---------------- epilogue ----------------
#pragma unroll
    for (int mt = 0; mt < MT; mt++) {
        const int r0 = mBlock + wmB + mt * 16 + g;
#pragma unroll
        for (int nt = 0; nt < NT; nt++) {
            const int c0 = nBlock + wnB + nt * 8 + 2 * t4;
            float bb0 = bias1[c0]     + (DUAL ? bias2[c0]     : 0.f);
            float bb1 = bias1[c0 + 1] + (DUAL ? bias2[c0 + 1] : 0.f);
            float v00 = acc[mt][nt][0] + bb0;
            float v01 = acc[mt][nt][1] + bb1;
            float v10 = acc[mt][nt][2] + bb0;
            float v11 = acc[mt][nt][3] + bb1;
            if (TANH) {
                v00 = tanhf(v00); v01 = tanhf(v01);
                v10 = tanhf(v10); v11 = tanhf(v11);
                bf16 h00 = __float2bfloat16(v00), h01 = __float2bfloat16(v01);
                bf16 h10 = __float2bfloat16(v10), h11 = __float2bfloat16(v11);
                bf16 l00 = __float2bfloat16(v00 - __bfloat162float(h00));
                bf16 l01 = __float2bfloat16(v01 - __bfloat162float(h01));
                bf16 l10 = __float2bfloat16(v10 - __bfloat162float(h10));
                bf16 l11 = __float2bfloat16(v11 - __bfloat162float(h11));
                *(__nv_bfloat162*)&Ch[(size_t)r0 * N + c0]       = __halves2bfloat162(h00, h01);
                *(__nv_bfloat162*)&Ch[(size_t)(r0 + 8) * N + c0] = __halves2bfloat162(h10, h11);
                *(__nv_bfloat162*)&Cl[(size_t)r0 * N + c0]       = __halves2bfloat162(l00, l01);
                *(__nv_bfloat162*)&Cl[(size_t)(r0 + 8) * N + c0] = __halves2bfloat162(l10, l11);
            } else {
                *(float2*)&Cf[(size_t)r0 * N + c0]       = make_float2(v00, v01);
                *(float2*)&Cf[(size_t)(r0 + 8) * N + c0] = make_float2(v10, v11);
            }
        }
    }
}

// ---------------- host driver ----------------
extern "C" void kernel_launch(void* const* d_in, const int* in_sizes, int n_in,
                              void* d_out, int out_size)
{
    const float* x      = (const float*)d_in[0];
    const float* hidden = (const float*)d_in[1];
    const float* Wih    = (const float*)d_in[3];
    const float* Whh    = (const float*)d_in[4];
    const float* bih    = (const float*)d_in[5];
    const float* bhh    = (const float*)d_in[6];
    const float* fcW    = (const float*)d_in[7];
    const float* fcb    = (const float*)d_in[8];
    float* out = (float*)d_out;

    const int T = in_sizes[2] / (BATCH * HD);   // embedded only sets T

    bf16 *pWih_h, *pWih_l, *pWhh_h, *pWhh_l, *pfcW_h, *pfcW_l;
    bf16 *pX_h, *pX_l, *pHid_h, *pHid_l, *pH0_h, *pH0_l, *pOut_h, *pOut_l;
    cudaGetSymbolAddress((void**)&pWih_h, g_Wih_h);
    cudaGetSymbolAddress((void**)&pWih_l, g_Wih_l);
    cudaGetSymbolAddress((void**)&pWhh_h, g_Whh_h);
    cudaGetSymbolAddress((void**)&pWhh_l, g_Whh_l);
    cudaGetSymbolAddress((void**)&pfcW_h, g_fcW_h);
    cudaGetSymbolAddress((void**)&pfcW_l, g_fcW_l);
    cudaGetSymbolAddress((void**)&pX_h,   g_x_h);
    cudaGetSymbolAddress((void**)&pX_l,   g_x_l);
    cudaGetSymbolAddress((void**)&pHid_h, g_hid_h);
    cudaGetSymbolAddress((void**)&pHid_l, g_hid_l);
    cudaGetSymbolAddress((void**)&pH0_h,  g_h0_h);
    cudaGetSymbolAddress((void**)&pH0_l,  g_h0_l);
    cudaGetSymbolAddress((void**)&pOut_h, g_out_h);
    cudaGetSymbolAddress((void**)&pOut_l, g_out_l);

    // split weights + initial activations into bf16 (hi, lo) pairs
    split_kernel<<<2048, 256>>>(Wih,    pWih_h, pWih_l, 2 * HD * HD);
    split_kernel<<<2048, 256>>>(Whh,    pWhh_h, pWhh_l, 2 * HD * HD);
    split_kernel<<<4096, 256>>>(fcW,    pfcW_h, pfcW_l, OD * HD);
    split_kernel<<<256,  256>>>(x,      pX_h,   pX_l,   BATCH * HD);
    split_kernel<<<512,  256>>>(hidden, pHid_h, pHid_l, 2 * BATCH * HD);

    const dim3 gridL(HD / 64, BATCH / 32), blockL(128);   // 128 blocks, 4 warps
    const dim3 gridF(OD / 128, BATCH / 64), blockF(128);  // 256 blocks, 4 warps
    const size_t S  = (size_t)BATCH * HD;
    const size_t W1 = (size_t)HD * HD;

    for (int t = 0; t < T; t++) {
        const size_t po = ((t - 1) & 1) * S;   // previous ping-pong offset
        const size_t pn = (t & 1) * S;         // current  ping-pong offset
        const bf16* in_h  = t ? pOut_h + po : pX_h;
        const bf16* in_l  = t ? pOut_l + po : pX_l;
        const bf16* h0p_h = t ? pH0_h  + po : pHid_h;
        const bf16* h0p_l = t ? pH0_l  + po : pHid_l;
        const bf16* h1p_h = t ? pOut_h + po : pHid_h + S;
        const bf16* h1p_l = t ? pOut_l + po : pHid_l + S;

        // layer 0: h0 = tanh(in@Wih0^T + bih0 + h0p@Whh0^T + bhh0)
        gemm_bf16s<32, 64, 16, 32, 2, 2, true, true><<<gridL, blockL>>>(
            in_h, in_l, pWih_h, pWih_l, h0p_h, h0p_l, pWhh_h, pWhh_l,
            bih, bhh, pH0_h + pn, pH0_l + pn, nullptr, HD, HD);
        // layer 1: out = tanh(h0@Wih1^T + bih1 + h1p@Whh1^T + bhh1)
        gemm_bf16s<32, 64, 16, 32, 2, 2, true, true><<<gridL, blockL>>>(
            pH0_h + pn, pH0_l + pn, pWih_h + W1, pWih_l + W1,
            h1p_h, h1p_l, pWhh_h + W1, pWhh_l + W1,
            bih + HD, bhh + HD, pOut_h + pn, pOut_l + pn, nullptr, HD, HD);
        // fc: logits_t = out@fcW^T + fcb -> d_out[t]
        gemm_bf16s<64, 128, 32, 64, 2, 2, false, false><<<gridF, blockF>>>(
            pOut_h + pn, pOut_l + pn, pfcW_h, pfcW_l,
            nullptr, nullptr, nullptr, nullptr,
            fcb, nullptr, nullptr, nullptr,
            out + (size_t)t * BATCH * OD, HD, OD);
    }
}

// round 8
// speedup vs baseline: 1.0231x; 1.0231x over previous
#include <cuda_runtime.h>
#include <cuda_bf16.h>
#include <cstdint>
#include <cstddef>

#define HD    1024
#define OD    8192
#define BATCH 256
#define TMAX  64

typedef __nv_bfloat16 bf16;

// ---------------- persistent device scratch (no runtime allocation) ----------------
__device__ __align__(16) bf16 g_Wih_h[2 * HD * HD];
__device__ __align__(16) bf16 g_Wih_l[2 * HD * HD];
__device__ __align__(16) bf16 g_Whh_h[2 * HD * HD];
__device__ __align__(16) bf16 g_Whh_l[2 * HD * HD];
__device__ __align__(16) bf16 g_fcW_h[(size_t)OD * HD];
__device__ __align__(16) bf16 g_fcW_l[(size_t)OD * HD];
__device__ __align__(16) bf16 g_x_h [BATCH * HD];
__device__ __align__(16) bf16 g_x_l [BATCH * HD];
__device__ __align__(16) bf16 g_hid_h[2 * BATCH * HD];
__device__ __align__(16) bf16 g_hid_l[2 * BATCH * HD];
__device__ __align__(16) bf16 g_h0_h[2 * BATCH * HD];            // ping-pong layer-0 state
__device__ __align__(16) bf16 g_h0_l[2 * BATCH * HD];
__device__ __align__(16) bf16 g_out_h[(size_t)TMAX * BATCH * HD]; // depth-T: no cross-stream hazard
__device__ __align__(16) bf16 g_out_l[(size_t)TMAX * BATCH * HD];

// ---------------- small PTX helpers ----------------
__device__ __forceinline__ void cp_async16(void* sm, const void* gm) {
    unsigned s = (unsigned)__cvta_generic_to_shared(sm);
    asm volatile("cp.async.cg.shared.global [%0], [%1], 16;\n" :: "r"(s), "l"(gm));
}
__device__ __forceinline__ void cp_commit() { asm volatile("cp.async.commit_group;\n"); }
template<int N> __device__ __forceinline__ void cp_wait() {
    asm volatile("cp.async.wait_group %0;\n" :: "n"(N));
}
__device__ __forceinline__ void mma_bf16(float* c, const uint32_t* a, const uint32_t* b) {
    asm volatile(
        "mma.sync.aligned.m16n8k16.row.col.f32.bf16.bf16.f32 "
        "{%0,%1,%2,%3},{%4,%5,%6,%7},{%8,%9},{%0,%1,%2,%3};\n"
        : "+f"(c[0]), "+f"(c[1]), "+f"(c[2]), "+f"(c[3])
        : "r"(a[0]), "r"(a[1]), "r"(a[2]), "r"(a[3]), "r"(b[0]), "r"(b[1]));
}

// ---------------- fp32 -> (hi,lo) bf16 split ----------------
__global__ void split_kernel(const float* __restrict__ src,
                             bf16* __restrict__ h, bf16* __restrict__ l, int n) {
    for (int i = blockIdx.x * blockDim.x + threadIdx.x; i < n; i += gridDim.x * blockDim.x) {
        float v = src[i];
        bf16 hv = __float2bfloat16(v);
        h[i] = hv;
        l[i] = __float2bfloat16(v - __bfloat162float(hv));
    }
}

// ---------------- split-bf16 tiled GEMM (multi-stage, 1 barrier/iter) ----------------
// C = A1@W1^T (+ A2@W2^T) + bias1 (+bias2), computed as Ah*Bh + Ah*Bl + Al*Bh.
// A row-major [M,K]; W row-major [N,K]. Dual phases fused along a virtual 2K axis.
// TANH: writes (hi,lo) bf16 pairs to Ch/Cl. Else: fp32 to Cf.
template<int BM, int BN, int BK, int STAGES, int WM, int WN, int WARPS_M, int WARPS_N,
         bool DUAL, bool TANH>
__global__ void __launch_bounds__(WARPS_M * WARPS_N * 32)
gemm_bf16s(const bf16* __restrict__ A1h, const bf16* __restrict__ A1l,
           const bf16* __restrict__ W1h, const bf16* __restrict__ W1l,
           const bf16* __restrict__ A2h, const bf16* __restrict__ A2l,
           const bf16* __restrict__ W2h, const bf16* __restrict__ W2l,
           const float* __restrict__ bias1, const float* __restrict__ bias2,
           bf16* __restrict__ Ch, bf16* __restrict__ Cl, float* __restrict__ Cf,
           int K, int N)
{
    constexpr int THREADS = WARPS_M * WARPS_N * 32;
    constexpr int BKP  = BK + 8;           // pad: stride/2 words per row, conflict-free frag reads
    constexpr int ROWS = BM + BN;          // A rows then B rows in one tile
    constexpr int MT = WM / 16, NT = WN / 8;
    constexpr int CH = BK / 8;             // 16B chunks per row
    constexpr int TOTC = ROWS * CH;

    __shared__ __align__(16) bf16 Sh[STAGES][ROWS][BKP];
    __shared__ __align__(16) bf16 Sl[STAGES][ROWS][BKP];

    const int tid  = threadIdx.x;
    const int lane = tid & 31;
    const int warp = tid >> 5;
    const int g    = lane >> 2;
    const int t4   = lane & 3;
    const int wmB  = (warp / WARPS_N) * WM;
    const int wnB  = (warp % WARPS_N) * WN;
    const int mBlock = blockIdx.y * BM;
    const int nBlock = blockIdx.x * BN;

    const int steps = (DUAL ? 2 * K : K) / BK;

    auto load_stage = [&](int st, int kbase) {
        const bf16 *Ah, *Al, *Wh, *Wl;
        int ko;
        if (DUAL && kbase >= K) { Ah = A2h; Al = A2l; Wh = W2h; Wl = W2l; ko = kbase - K; }
        else                    { Ah = A1h; Al = A1l; Wh = W1h; Wl = W1l; ko = kbase; }
        const bf16* Abh = Ah + (size_t)mBlock * K + ko;
        const bf16* Abl = Al + (size_t)mBlock * K + ko;
        const bf16* Bbh = Wh + (size_t)nBlock * K + ko;
        const bf16* Bbl = Wl + (size_t)nBlock * K + ko;
#pragma unroll
        for (int i = tid; i < TOTC; i += THREADS) {
            int r = i / CH, c = (i % CH) * 8;
            const bf16* gh = (r < BM) ? Abh + (size_t)r * K + c : Bbh + (size_t)(r - BM) * K + c;
            const bf16* gl = (r < BM) ? Abl + (size_t)r * K + c : Bbl + (size_t)(r - BM) * K + c;
            cp_async16(&Sh[st][r][c], gh);
            cp_async16(&Sl[st][r][c], gl);
        }
    };

    float acc[MT][NT][4];
#pragma unroll
    for (int i = 0; i < MT; i++)
#pragma unroll
        for (int j = 0; j < NT; j++)
#pragma unroll
            for (int q = 0; q < 4; q++) acc[i][j][q] = 0.f;

    // prime STAGES-1 stages
#pragma unroll
    for (int s = 0; s < STAGES - 1; s++) { load_stage(s, s * BK); cp_commit(); }

    for (int kt = 0; kt < steps; kt++) {
        const int cur = kt % STAGES;
        cp_wait<STAGES - 2>();
        __syncthreads();                       // all warps done reading buffer (kt-1)%STAGES

        const int pf = kt + STAGES - 1;        // prefetch into the buffer just freed
        if (pf < steps) load_stage(pf % STAGES, pf * BK);
        cp_commit();                            // commit every iter (possibly empty) for uniform accounting

#pragma unroll
        for (int s = 0; s < BK / 16; s++) {
            const int k0 = s * 16;
            uint32_t ah[MT][4], al[MT][4], bh[NT][2], bl[NT][2];
#pragma unroll
            for (int mt = 0; mt < MT; mt++) {
                int r = wmB + mt * 16 + g;
                ah[mt][0] = *(const uint32_t*)&Sh[cur][r    ][k0 + 2 * t4];
                ah[mt][1] = *(const uint32_t*)&Sh[cur][r + 8][k0 + 2 * t4];
                ah[mt][2] = *(const uint32_t*)&Sh[cur][r    ][k0 + 2 * t4 + 8];
                ah[mt][3] = *(const uint32_t*)&Sh[cur][r + 8][k0 + 2 * t4 + 8];
                al[mt][0] = *(const uint32_t*)&Sl[cur][r    ][k0 + 2 * t4];
                al[mt][1] = *(const uint32_t*)&Sl[cur][r + 8][k0 + 2 * t4];
                al[mt][2] = *(const uint32_t*)&Sl[cur][r    ][k0 + 2 * t4 + 8];
                al[mt][3] = *(const uint32_t*)&Sl[cur][r + 8][k0 + 2 * t4 + 8];
            }
#pragma unroll
            for (int nt = 0; nt < NT; nt++) {
                int cc = BM + wnB + nt * 8 + g;
                bh[nt][0] = *(const uint32_t*)&Sh[cur][cc][k0 + 2 * t4];
                bh[nt][1] = *(const uint32_t*)&Sh[cur][cc][k0 + 2 * t4 + 8];
                bl[nt][0] = *(const uint32_t*)&Sl[cur][cc][k0 + 2 * t4];
                bl[nt][1] = *(const uint32_t*)&Sl[cur][cc][k0 + 2 * t4 + 8];
            }
#pragma unroll
            for (int mt = 0; mt < MT; mt++)
#pragma unroll
                for (int nt = 0; nt < NT; nt++) {
                    mma_bf16(acc[mt][nt], ah[mt], bh[nt]);   // hi*hi
                    mma_bf16(acc[mt][nt], ah[mt], bl[nt]);   // hi*lo
                    mma_bf16(acc[mt][nt], al[mt], bh[nt]);   // lo*hi
                }
        }
    }

    // ---------------- epilogue ----------------
#pragma unroll
    for (int mt = 0; mt < MT; mt++) {
        const int r0 = mBlock + wmB + mt * 16 + g;
#pragma unroll
        for (int nt = 0; nt < NT; nt++) {
            const int c0 = nBlock + wnB + nt * 8 + 2 * t4;
            float bb0 = bias1[c0]     + (DUAL ? bias2[c0]     : 0.f);
            float bb1 = bias1[c0 + 1] + (DUAL ? bias2[c0 + 1] : 0.f);
            float v00 = acc[mt][nt][0] + bb0;
            float v01 = acc[mt][nt][1] + bb1;
            float v10 = acc[mt][nt][2] + bb0;
            float v11 = acc[mt][nt][3] + bb1;
            if (TANH) {
                v00 = tanhf(v00); v01 = tanhf(v01);
                v10 = tanhf(v10); v11 = tanhf(v11);
                bf16 h00 = __float2bfloat16(v00), h01 = __float2bfloat16(v01);
                bf16 h10 = __float2bfloat16(v10), h11 = __float2bfloat16(v11);
                bf16 l00 = __float2bfloat16(v00 - __bfloat162float(h00));
                bf16 l01 = __float2bfloat16(v01 - __bfloat162float(h01));
                bf16 l10 = __float2bfloat16(v10 - __bfloat162float(h10));
                bf16 l11 = __float2bfloat16(v11 - __bfloat162float(h11));
                *(__nv_bfloat162*)&Ch[(size_t)r0 * N + c0]       = __halves2bfloat162(h00, h01);
                *(__nv_bfloat162*)&Ch[(size_t)(r0 + 8) * N + c0] = __halves2bfloat162(h10, h11);
                *(__nv_bfloat162*)&Cl[(size_t)r0 * N + c0]       = __halves2bfloat162(l00, l01);
                *(__nv_bfloat162*)&Cl[(size_t)(r0 + 8) * N + c0] = __halves2bfloat162(l10, l11);
            } else {
                *(float2*)&Cf[(size_t)r0 * N + c0]       = make_float2(v00, v01);
                *(float2*)&Cf[(size_t)(r0 + 8) * N + c0] = make_float2(v10, v11);
            }
        }
    }
}

// ---------------- host driver ----------------
extern "C" void kernel_launch(void* const* d_in, const int* in_sizes, int n_in,
                              void* d_out, int out_size)
{
    const float* x      = (const float*)d_in[0];
    const float* hidden = (const float*)d_in[1];
    const float* Wih    = (const float*)d_in[3];
    const float* Whh    = (const float*)d_in[4];
    const float* bih    = (const float*)d_in[5];
    const float* bhh    = (const float*)d_in[6];
    const float* fcW    = (const float*)d_in[7];
    const float* fcb    = (const float*)d_in[8];
    float* out = (float*)d_out;

    int T = in_sizes[2] / (BATCH * HD);
    if (T > TMAX) T = TMAX;

    bf16 *pWih_h, *pWih_l, *pWhh_h, *pWhh_l, *pfcW_h, *pfcW_l;
    bf16 *pX_h, *pX_l, *pHid_h, *pHid_l, *pH0_h, *pH0_l, *pOut_h, *pOut_l;
    cudaGetSymbolAddress((void**)&pWih_h, g_Wih_h);
    cudaGetSymbolAddress((void**)&pWih_l, g_Wih_l);
    cudaGetSymbolAddress((void**)&pWhh_h, g_Whh_h);
    cudaGetSymbolAddress((void**)&pWhh_l, g_Whh_l);
    cudaGetSymbolAddress((void**)&pfcW_h, g_fcW_h);
    cudaGetSymbolAddress((void**)&pfcW_l, g_fcW_l);
    cudaGetSymbolAddress((void**)&pX_h,   g_x_h);
    cudaGetSymbolAddress((void**)&pX_l,   g_x_l);
    cudaGetSymbolAddress((void**)&pHid_h, g_hid_h);
    cudaGetSymbolAddress((void**)&pHid_l, g_hid_l);
    cudaGetSymbolAddress((void**)&pH0_h,  g_h0_h);
    cudaGetSymbolAddress((void**)&pH0_l,  g_h0_l);
    cudaGetSymbolAddress((void**)&pOut_h, g_out_h);
    cudaGetSymbolAddress((void**)&pOut_l, g_out_l);

    // second stream + fork/join events (leaked; a handful of kernel_launch calls total)
    cudaStream_t s2;
    cudaStreamCreateWithFlags(&s2, cudaStreamNonBlocking);
    cudaEvent_t evFork, evJoin;
    cudaEventCreateWithFlags(&evFork, cudaEventDisableTiming);
    cudaEventCreateWithFlags(&evJoin, cudaEventDisableTiming);

    // split weights + initial activations into bf16 (hi, lo) pairs
    split_kernel<<<2048, 256>>>(Wih,    pWih_h, pWih_l, 2 * HD * HD);
    split_kernel<<<2048, 256>>>(Whh,    pWhh_h, pWhh_l, 2 * HD * HD);
    split_kernel<<<4096, 256>>>(fcW,    pfcW_h, pfcW_l, OD * HD);
    split_kernel<<<256,  256>>>(x,      pX_h,   pX_l,   BATCH * HD);
    split_kernel<<<512,  256>>>(hidden, pHid_h, pHid_l, 2 * BATCH * HD);

    const dim3 gridL(HD / 64, BATCH / 32), blockL(128);   // 128 blocks, 4 warps
    const dim3 gridF(OD / 128, BATCH / 64), blockF(128);  // 256 blocks, 4 warps
    const size_t S  = (size_t)BATCH * HD;
    const size_t W1 = (size_t)HD * HD;

    for (int t = 0; t < T; t++) {
        const size_t pn = (size_t)(t & 1) * S;       // h0 ping-pong (stream-1 internal only)
        const bf16* in_h  = t ? pOut_h + (size_t)(t - 1) * S : pX_h;
        const bf16* in_l  = t ? pOut_l + (size_t)(t - 1) * S : pX_l;
        const bf16* h0p_h = t ? pH0_h + (size_t)((t - 1) & 1) * S : pHid_h;
        const bf16* h0p_l = t ? pH0_l + (size_t)((t - 1) & 1) * S : pHid_l;
        const bf16* h1p_h = t ? pOut_h + (size_t)(t - 1) * S : pHid_h + S;
        const bf16* h1p_l = t ? pOut_l + (size_t)(t - 1) * S : pHid_l + S;

        // layer 0: h0 = tanh(in@Wih0^T + bih0 + h0p@Whh0^T + bhh0)     [BK=32, 3-stage]
        gemm_bf16s<32, 64, 32, 3, 16, 32, 2, 2, true, true><<<gridL, blockL>>>(
            in_h, in_l, pWih_h, pWih_l, h0p_h, h0p_l, pWhh_h, pWhh_l,
            bih, bhh, pH0_h + pn, pH0_l + pn, nullptr, HD, HD);
        // layer 1: out[t] = tanh(h0@Wih1^T + bih1 + h1p@Whh1^T + bhh1)
        gemm_bf16s<32, 64, 32, 3, 16, 32, 2, 2, true, true><<<gridL, blockL>>>(
            pH0_h + pn, pH0_l + pn, pWih_h + W1, pWih_l + W1,
            h1p_h, h1p_l, pWhh_h + W1, pWhh_l + W1,
            bih + HD, bhh + HD, pOut_h + (size_t)t * S, pOut_l + (size_t)t * S, nullptr, HD, HD);

        // fc on stream 2, forked after layer 1 (off the critical path)
        cudaEventRecord(evFork, 0);
        cudaStreamWaitEvent(s2, evFork, 0);
        gemm_bf16s<64, 128, 16, 2, 32, 64, 2, 2, false, false><<<gridF, blockF, 0, s2>>>(
            pOut_h + (size_t)t * S, pOut_l + (size_t)t * S, pfcW_h, pfcW_l,
            nullptr, nullptr, nullptr, nullptr,
            fcb, nullptr, nullptr, nullptr,
            out + (size_t)t * BATCH * OD, HD, OD);
    }

    // join: main stream waits for all fc work before returning control to harness
    cudaEventRecord(evJoin, s2);
    cudaStreamWaitEvent(0, evJoin, 0);
}